// round 4
// baseline (speedup 1.0000x reference)
#include <cuda_runtime.h>
#include <math.h>

// CTC forward loss, log2-domain DP (numerically exact logsumexp recurrence).
// log_probs (T=512, N=512, C=80) f32; targets (N, S=128) i32; lengths (N) i32.
// Output (N,) f32.  Lattice L = 2S+1 = 257.
// One warp per batch element; 10 lattice positions per thread (32*10=320>=257).
// PPT=10 (even) makes register-index parity == lattice parity:
//   j even -> blank cell (2-term LSE), j odd -> label cell (3-term LSE).

#define TT 512
#define NN 512
#define CC 80
#define SS 128
#define LL 257
#define PPT 10
#define ROWSTRIDE 84   // floats per smem emission row (80 data + [80..83]=0 pad)
#define CHUNK 8        // time steps per prefetch chunk
#define WPB 4          // warps per block

#define NEGF  (-1.0e4f)   // "log-zero" init (stays >=7000 log2 below any real cell)
#define NEG2F (-1.0e5f)   // skip-blocked sentinel (ex2 -> 0 exactly)
#define LOG2E 1.4426950408889634f
#define LN2   0.6931471805599453f

__device__ __forceinline__ float ex2f(float x) {
    float r; asm("ex2.approx.ftz.f32 %0, %1;" : "=f"(r) : "f"(x)); return r;
}
__device__ __forceinline__ float lg2f(float x) {
    float r; asm("lg2.approx.ftz.f32 %0, %1;" : "=f"(r) : "f"(x)); return r;
}

// 2-term LSE in log2 domain: log2(2^x + 2^y)
__device__ __forceinline__ float lse2(float x, float y) {
    float m = fmaxf(x, y);
    float d = fminf(x, y) - m;            // <= 0
    return m + lg2f(1.0f + ex2f(d));
}
// 3-term LSE in log2 domain (max delta is exactly 0; mid via exact median-of-3)
__device__ __forceinline__ float lse3(float x, float y, float z) {
    float m  = fmaxf(fmaxf(x, y), z);
    float d0 = x - m, d1 = y - m, d2 = z - m;     // one of these == 0
    float t1 = fminf(d0, d1), t2 = fmaxf(d0, d1);
    float dmin = fminf(t1, d2);
    float dmid = fminf(t2, fmaxf(t1, d2));        // median (exact, no cancellation)
    return m + lg2f(1.0f + ex2f(dmin) + ex2f(dmid));
}

__global__ __launch_bounds__(128, 1)
void ctc_kernel(const float* __restrict__ lp,
                const int*   __restrict__ targets,
                const int*   __restrict__ lenA,
                const int*   __restrict__ lenB,
                float*       __restrict__ out)
{
    __shared__ __align__(16) float pbuf[WPB][2][CHUNK][ROWSTRIDE];
    __shared__ int   stgt[WPB][SS];
    __shared__ float salpha[WPB][32 * PPT];

    const int warp = threadIdx.x >> 5;
    const int lane = threadIdx.x & 31;
    const int n    = blockIdx.x * WPB + warp;   // 128 blocks * 4 warps = 512

    // Length roles: ranges are disjoint (T_in in [256,512], tl in [64,128]).
    const int la = lenA[n];
    const int lb = lenB[n];
    int T_in = la > lb ? la : lb;
    int tl   = la > lb ? lb : la;
    T_in = max(1, min(T_in, TT));
    tl   = max(1, min(tl, SS));

    for (int i = lane; i < SS; i += 32) {
        int y = targets[n * SS + i];
        stgt[warp][i] = max(0, min(y, CC - 1));
    }
    __syncwarp();

    // Per-thread lattice setup. s = lane*PPT + j.
    int   extoff[PPT];    // byte offset of emission class within a row (odd j); pad->320
    float skipok[PPT];    // odd j: 1.0 if skip transition allowed
    float a[PPT];
    #pragma unroll
    for (int j = 0; j < PPT; j++) {
        const int s = lane * PPT + j;
        int e = 80; float sk = 0.f;      // default: pad slot (row[80]=0)
        if (s < LL) {
            if ((s & 1) == 0) e = 0;     // blank
            else {
                e = stgt[warp][(s - 1) >> 1];
                if (s >= 3) sk = (e != stgt[warp][(s - 3) >> 1]) ? 1.f : 0.f;
            }
        }
        extoff[j] = e * 4;
        skipok[j] = sk;
        a[j]      = NEGF;
    }

    // t = 0 init (log2 units): only s=0 and s=1 reachable.
    if (lane == 0) {
        const float* row0 = lp + (size_t)n * CC;
        a[0] = row0[0] * LOG2E;
        a[1] = row0[stgt[warp][0]] * LOG2E;
    }

    // Chunk-load mapping: 8 rows x 20 float4 = 160 loads = 5 per lane.
    int rr[5], pq[5];
    #pragma unroll
    for (int k = 0; k < 5; k++) {
        const int q = lane + 32 * k;
        rr[k] = q / 20;
        pq[k] = q % 20;
    }

    float4 rbuf[5];
    #pragma unroll
    for (int k = 0; k < 5; k++) {       // prefetch chunk 0 (t = 1..8)
        int t = 1 + rr[k]; if (t > TT - 1) t = TT - 1;
        const float4* src = (const float4*)(lp + ((size_t)t * NN + n) * CC);
        rbuf[k] = src[pq[k]];
    }

    float* const myb0 = &pbuf[warp][0][0][0];
    float* const myb1 = &pbuf[warp][1][0][0];

    const int totalSteps = T_in - 1;    // DP steps at t = 1 .. T_in-1

    for (int c = 0; ; c++) {
        int nst = totalSteps - c * CHUNK;
        if (nst <= 0) break;
        if (nst > CHUNK) nst = CHUNK;
        const int t0 = 1 + c * CHUNK;

        float* const buf = (c & 1) ? myb1 : myb0;

        // store log2e-scaled log-probs to smem
        #pragma unroll
        for (int k = 0; k < 5; k++) {
            float4 v = rbuf[k];
            v.x *= LOG2E; v.y *= LOG2E; v.z *= LOG2E; v.w *= LOG2E;
            *(float4*)(buf + rr[k] * ROWSTRIDE + pq[k] * 4) = v;
        }
        if (lane < CHUNK) {
            *(float4*)(buf + lane * ROWSTRIDE + 80) = make_float4(0.f, 0.f, 0.f, 0.f);
        }

        if ((c + 1) * CHUNK < totalSteps) {     // prefetch next chunk
            #pragma unroll
            for (int k = 0; k < 5; k++) {
                int t = t0 + CHUNK + rr[k]; if (t > TT - 1) t = TT - 1;
                const float4* src = (const float4*)(lp + ((size_t)t * NN + n) * CC);
                rbuf[k] = src[pq[k]];
            }
        }
        __syncwarp();

        #pragma unroll
        for (int r = 0; r < CHUNK; r++) {
            if (r < nst) {
                const float* prow = buf + r * ROWSTRIDE;
                // up9 = a[s-1] for j=0, and a[s-2] (skip source) for j=1
                float up9 = __shfl_up_sync(0xffffffffu, a[PPT - 1], 1);
                if (lane == 0) up9 = NEGF;

                const float emB = prow[0];     // blank emission shared by even cells

                // descending j: reads see old values only
                #pragma unroll
                for (int j = PPT - 1; j >= 2; j--) {
                    const float em = (j & 1)
                        ? *(const float*)((const char*)prow + extoff[j]) : emB;
                    if (j & 1) {
                        float p2 = skipok[j] != 0.f ? a[j - 2] : NEG2F;
                        a[j] = lse3(a[j], a[j - 1], p2) + em;
                    } else {
                        a[j] = lse2(a[j], a[j - 1]) + em;
                    }
                }
                {   // j = 1: s-1 = own a[0] (old), s-2 = prev lane a[9] = up9
                    const float em = *(const float*)((const char*)prow + extoff[1]);
                    float p2 = skipok[1] != 0.f ? up9 : NEG2F;
                    a[1] = lse3(a[1], a[0], p2) + em;
                }
                {   // j = 0: s-1 = prev lane a[9] = up9
                    a[0] = lse2(a[0], up9) + emB;
                }
            }
        }
    }

    // Readout: alpha at s = 2*tl and 2*tl-1 at t = T_in-1.
    #pragma unroll
    for (int j = 0; j < PPT; j++) salpha[warp][lane * PPT + j] = a[j];
    __syncwarp();
    if (lane == 0) {
        const float v1 = salpha[warp][2 * tl];
        const float v2 = salpha[warp][2 * tl - 1];
        float loss = -LN2 * lse2(v1, v2);
        if (!isfinite(loss) || loss >= 1e10f) loss = 0.f;
        out[n] = loss;
    }
}

extern "C" void kernel_launch(void* const* d_in, const int* in_sizes, int n_in,
                              void* d_out, int out_size) {
    const float* lp      = nullptr;
    const int*   targets = nullptr;
    const int*   lenA    = nullptr;
    const int*   lenB    = nullptr;
    for (int i = 0; i < n_in; i++) {
        const int sz = in_sizes[i];
        if (sz == TT * NN * CC)      lp      = (const float*)d_in[i];
        else if (sz == NN * SS)      targets = (const int*)d_in[i];
        else if (sz == NN) { if (!lenA) lenA = (const int*)d_in[i];
                             else       lenB = (const int*)d_in[i]; }
    }
    if (!lp)      lp      = (const float*)d_in[0];
    if (!targets) targets = (const int*)d_in[1];
    if (!lenA)    lenA    = (const int*)d_in[2];
    if (!lenB)    lenB    = (const int*)d_in[3];

    float* out = (float*)d_out;
    (void)out_size;
    ctc_kernel<<<NN / WPB, 32 * WPB>>>(lp, targets, lenA, lenB, out);
}

// round 5
// speedup vs baseline: 1.4378x; 1.4378x over previous
#include <cuda_runtime.h>
#include <math.h>

// CTC forward loss — linear-domain DP with PER-THREAD integer-exponent frames.
// physical alpha = a' * 2^E  (a' fp32, E int per thread), renormalized every
// step by exponent-field extraction (no MUFU on the DP path).
// log_probs (T=512,N=512,C=80) f32; targets (N,128) i32; lengths (N) i32.
// One warp per batch element; 10 lattice positions/thread (32*10=320>=257).

#define TT 512
#define NN 512
#define CC 80
#define SS 128
#define LL 257
#define PPT 10
#define ROWSTRIDE 84
#define CHUNK 8
#define WPB 4

#define LOG2E 1.4426950408889634f
#define LN2   0.6931471805599453f

__device__ __forceinline__ float ex2f(float x) {
    float r; asm("ex2.approx.ftz.f32 %0, %1;" : "=f"(r) : "f"(x)); return r;
}
__device__ __forceinline__ float lg2f(float x) {
    float r; asm("lg2.approx.ftz.f32 %0, %1;" : "=f"(r) : "f"(x)); return r;
}
// log2(2^x + 2^y), tolerant of -inf inputs
__device__ __forceinline__ float lse2(float x, float y) {
    float m = fmaxf(x, y);
    float d = fminf(x, y) - m;
    return m + lg2f(1.0f + ex2f(d));
}

__global__ __launch_bounds__(128, 1)
void ctc_kernel(const float* __restrict__ lp,
                const int*   __restrict__ targets,
                const int*   __restrict__ lenA,
                const int*   __restrict__ lenB,
                float*       __restrict__ out)
{
    __shared__ __align__(16) float pbuf[WPB][2][CHUNK][ROWSTRIDE];
    __shared__ int   stgt[WPB][SS];
    __shared__ float salpha[WPB][32 * PPT];
    __shared__ int   sE[WPB][32];

    const int warp = threadIdx.x >> 5;
    const int lane = threadIdx.x & 31;
    const int n    = blockIdx.x * WPB + warp;

    // Length roles: ranges disjoint (T_in in [256,512], tl in [64,128]).
    const int la = lenA[n];
    const int lb = lenB[n];
    int T_in = la > lb ? la : lb;
    int tl   = la > lb ? lb : la;
    T_in = max(1, min(T_in, TT));
    tl   = max(1, min(tl, SS));

    for (int i = lane; i < SS; i += 32) {
        int y = targets[n * SS + i];
        stgt[warp][i] = max(0, min(y, CC - 1));
    }
    __syncwarp();

    // Per-thread lattice setup. s = lane*PPT + j; j parity == lattice parity.
    int   extoff[PPT];      // emission byte offset (odd j); pad slot -> 320 (p=0)
    float skipok[PPT];
    float a[PPT];
    #pragma unroll
    for (int j = 0; j < PPT; j++) {
        const int s = lane * PPT + j;
        int e = 80; float sk = 0.f;
        if (s < LL) {
            if ((s & 1) == 0) e = 0;
            else {
                e = stgt[warp][(s - 1) >> 1];
                if (s >= 3) sk = (e != stgt[warp][(s - 3) >> 1]) ? 1.f : 0.f;
            }
        }
        extoff[j] = e * 4;
        skipok[j] = sk;
        a[j]      = 0.f;
    }

    int   E = 0;            // frame exponent: physical = a' * 2^E
    float prevmax = 0.f;    // thread-local max of current cells (frame-adoption flag)

    if (lane == 0) {
        const float* row0 = lp + (size_t)n * CC;
        a[0] = ex2f(row0[0] * LOG2E);
        a[1] = ex2f(row0[stgt[warp][0]] * LOG2E);
        prevmax = fmaxf(a[0], a[1]);
    }

    // Chunk-load mapping: 8 rows x 20 float4 = 160 loads = 5 per lane.
    int rr[5], pq[5];
    #pragma unroll
    for (int k = 0; k < 5; k++) {
        const int q = lane + 32 * k;
        rr[k] = q / 20;
        pq[k] = q % 20;
    }

    float4 rbuf[5];
    #pragma unroll
    for (int k = 0; k < 5; k++) {
        int t = 1 + rr[k]; if (t > TT - 1) t = TT - 1;
        const float4* src = (const float4*)(lp + ((size_t)t * NN + n) * CC);
        rbuf[k] = src[pq[k]];
    }

    float* const myb0 = &pbuf[warp][0][0][0];
    float* const myb1 = &pbuf[warp][1][0][0];

    const int totalSteps = T_in - 1;

    for (int c = 0; ; c++) {
        int nst = totalSteps - c * CHUNK;
        if (nst <= 0) break;
        if (nst > CHUNK) nst = CHUNK;
        const int t0 = 1 + c * CHUNK;

        float* const buf = (c & 1) ? myb1 : myb0;

        // exp to linear probabilities and store to smem
        #pragma unroll
        for (int k = 0; k < 5; k++) {
            float4 v = rbuf[k];
            v.x = ex2f(v.x * LOG2E); v.y = ex2f(v.y * LOG2E);
            v.z = ex2f(v.z * LOG2E); v.w = ex2f(v.w * LOG2E);
            *(float4*)(buf + rr[k] * ROWSTRIDE + pq[k] * 4) = v;
        }
        if (lane < CHUNK) {
            *(float4*)(buf + lane * ROWSTRIDE + 80) = make_float4(0.f, 0.f, 0.f, 0.f);
        }

        if ((c + 1) * CHUNK < totalSteps) {
            #pragma unroll
            for (int k = 0; k < 5; k++) {
                int t = t0 + CHUNK + rr[k]; if (t > TT - 1) t = TT - 1;
                const float4* src = (const float4*)(lp + ((size_t)t * NN + n) * CC);
                rbuf[k] = src[pq[k]];
            }
        }
        __syncwarp();

        #pragma unroll
        for (int r = 0; r < CHUNK; r++) {
            if (r < nst) {
                const float* prow = buf + r * ROWSTRIDE;

                float up = __shfl_up_sync(0xffffffffu, a[PPT - 1], 1);
                int   Ep = __shfl_up_sync(0xffffffffu, E, 1);

                // Frozen thread adopts neighbor's frame (cells all zero).
                if (lane > 0 && prevmax == 0.f) E = Ep;
                int dE = Ep - E;
                dE = min(max(dE, -126), 120);
                const float fup = __int_as_float((dE + 127) << 23);
                up = (lane == 0) ? 0.f : up * fup;

                const float pB = prow[0];

                float na[PPT];
                na[0] = (a[0] + up) * pB;
                {
                    const float p1 = *(const float*)((const char*)prow + extoff[1]);
                    na[1] = fmaf(skipok[1], up, a[1] + a[0]) * p1;
                }
                #pragma unroll
                for (int j = 2; j < PPT; j++) {
                    if (j & 1) {
                        const float pj = *(const float*)((const char*)prow + extoff[j]);
                        na[j] = fmaf(skipok[j], a[j - 2], a[j] + a[j - 1]) * pj;
                    } else {
                        na[j] = (a[j] + a[j - 1]) * pB;
                    }
                }

                // Per-thread renorm by exponent of max (exact power of two).
                float m = na[0];
                #pragma unroll
                for (int j = 1; j < PPT; j++) m = fmaxf(m, na[j]);
                int e = (m > 0.f) ? ((__float_as_int(m) >> 23) - 127) : 0;
                const float s = __int_as_float((127 - e) << 23);   // 2^-e
                #pragma unroll
                for (int j = 0; j < PPT; j++) a[j] = na[j] * s;
                E += e;
                prevmax = m;
            }
        }
    }

    // Readout: alpha at s = 2*tl and 2*tl-1 (may straddle two threads).
    #pragma unroll
    for (int j = 0; j < PPT; j++) salpha[warp][lane * PPT + j] = a[j];
    sE[warp][lane] = E;
    __syncwarp();
    if (lane == 0) {
        const int s1 = 2 * tl, s2 = 2 * tl - 1;
        const float v1 = salpha[warp][s1];
        const float v2 = salpha[warp][s2];
        const float l1 = lg2f(v1) + (float)sE[warp][s1 / PPT];
        const float l2 = lg2f(v2) + (float)sE[warp][s2 / PPT];
        float loss = -LN2 * lse2(l1, l2);
        if (!isfinite(loss) || loss >= 1e10f) loss = 0.f;
        out[n] = loss;
    }
}

extern "C" void kernel_launch(void* const* d_in, const int* in_sizes, int n_in,
                              void* d_out, int out_size) {
    const float* lp      = nullptr;
    const int*   targets = nullptr;
    const int*   lenA    = nullptr;
    const int*   lenB    = nullptr;
    for (int i = 0; i < n_in; i++) {
        const int sz = in_sizes[i];
        if (sz == TT * NN * CC)      lp      = (const float*)d_in[i];
        else if (sz == NN * SS)      targets = (const int*)d_in[i];
        else if (sz == NN) { if (!lenA) lenA = (const int*)d_in[i];
                             else       lenB = (const int*)d_in[i]; }
    }
    if (!lp)      lp      = (const float*)d_in[0];
    if (!targets) targets = (const int*)d_in[1];
    if (!lenA)    lenA    = (const int*)d_in[2];
    if (!lenB)    lenB    = (const int*)d_in[3];

    float* out = (float*)d_out;
    (void)out_size;
    ctc_kernel<<<NN / WPB, 32 * WPB>>>(lp, targets, lenA, lenB, out);
}

// round 6
// speedup vs baseline: 2.3004x; 1.6000x over previous
#include <cuda_runtime.h>
#include <math.h>

// CTC forward loss — linear-domain DP, per-thread integer-exponent frames.
// physical alpha = a' * 2^E.  Renorm + cross-thread frame refresh every 4
// steps; branch-free fully-unrolled 8-step chunks so ptxas can pipeline the
// shfl (wedge j=0,1 only; 4 steps of slack) against the local FMA chain.
// One warp per batch element; 10 lattice positions/thread (32*10=320>=257).

#define TT 512
#define NN 512
#define CC 80
#define SS 128
#define LL 257
#define PPT 10
#define ROWSTRIDE 84
#define CHUNK 8
#define WPB 4

#define LOG2E 1.4426950408889634f
#define LN2   0.6931471805599453f

__device__ __forceinline__ float ex2f(float x) {
    float r; asm("ex2.approx.ftz.f32 %0, %1;" : "=f"(r) : "f"(x)); return r;
}
__device__ __forceinline__ float lg2f(float x) {
    float r; asm("lg2.approx.ftz.f32 %0, %1;" : "=f"(r) : "f"(x)); return r;
}
__device__ __forceinline__ float lse2(float x, float y) {
    float m = fmaxf(x, y);
    float d = fminf(x, y) - m;
    return m + lg2f(1.0f + ex2f(d));
}

__global__ __launch_bounds__(128, 1)
void ctc_kernel(const float* __restrict__ lp,
                const int*   __restrict__ targets,
                const int*   __restrict__ lenA,
                const int*   __restrict__ lenB,
                float*       __restrict__ out)
{
    __shared__ __align__(16) float pbuf[WPB][2][CHUNK][ROWSTRIDE];
    __shared__ int   stgt[WPB][SS];
    __shared__ float salpha[WPB][32 * PPT];
    __shared__ int   sE[WPB][32];

    const int warp = threadIdx.x >> 5;
    const int lane = threadIdx.x & 31;
    const int n    = blockIdx.x * WPB + warp;

    // Length roles: ranges disjoint (T_in in [256,512], tl in [64,128]).
    const int la = lenA[n];
    const int lb = lenB[n];
    int T_in = la > lb ? la : lb;
    int tl   = la > lb ? lb : la;
    T_in = max(1, min(T_in, TT));
    tl   = max(1, min(tl, SS));

    for (int i = lane; i < SS; i += 32) {
        int y = targets[n * SS + i];
        stgt[warp][i] = max(0, min(y, CC - 1));
    }
    __syncwarp();

    // Lattice setup: s = lane*PPT + j; j parity == lattice parity.
    int   extoff[PPT];
    float skipok[PPT];
    float a[PPT];
    #pragma unroll
    for (int j = 0; j < PPT; j++) {
        const int s = lane * PPT + j;
        int e = 80; float sk = 0.f;
        if (s < LL) {
            if ((s & 1) == 0) e = 0;
            else {
                e = stgt[warp][(s - 1) >> 1];
                if (s >= 3) sk = (e != stgt[warp][(s - 3) >> 1]) ? 1.f : 0.f;
            }
        }
        extoff[j] = e * 4;
        skipok[j] = sk;
        a[j]      = 0.f;
    }

    int   E      = 0;
    float fup    = 1.f;              // 2^(Ep-E), refreshed at renorm cadence
    bool  active = (lane == 0);

    if (lane == 0) {
        const float* row0 = lp + (size_t)n * CC;
        a[0] = ex2f(row0[0] * LOG2E);
        a[1] = ex2f(row0[stgt[warp][0]] * LOG2E);
    }

    // Chunk-load mapping: 8 rows x 20 float4 = 160 loads = 5 per lane.
    int rr[5], pq[5];
    #pragma unroll
    for (int k = 0; k < 5; k++) {
        const int q = lane + 32 * k;
        rr[k] = q / 20;
        pq[k] = q % 20;
    }

    float4 rbuf[5];
    #pragma unroll
    for (int k = 0; k < 5; k++) {
        int t = 1 + rr[k]; if (t > TT - 1) t = TT - 1;
        const float4* src = (const float4*)(lp + ((size_t)t * NN + n) * CC);
        rbuf[k] = src[pq[k]];
    }

    float* const myb0 = &pbuf[warp][0][0][0];
    float* const myb1 = &pbuf[warp][1][0][0];

    const int totalSteps = T_in - 1;
    const int nchunks = (totalSteps + CHUNK - 1) / CHUNK;
    const int nfull   = totalSteps / CHUNK;

    // Frame refresh: Ep/E constant between renorms, so fup is hoisted here.
    #define REFRESH() do {                                                   \
        int Ep_ = __shfl_up_sync(0xffffffffu, E, 1);                         \
        if (!active) E = Ep_;                                                \
        int dE_ = min(max(Ep_ - E, -126), 120);                              \
        fup = __int_as_float((dE_ + 127) << 23);                             \
    } while (0)

    // One DP step. In-place descending update (reads lower-j old values).
    #define STEP(prow_, DORENORM) do {                                       \
        const float* prow = (prow_);                                         \
        float up = __shfl_up_sync(0xffffffffu, a[9], 1);                     \
        up = (lane == 0) ? 0.f : up * fup;                                   \
        if (!active && up != 0.f) active = true;                             \
        const float pB = prow[0];                                            \
        const float p9 = *(const float*)((const char*)prow + extoff[9]);     \
        const float p7 = *(const float*)((const char*)prow + extoff[7]);     \
        const float p5 = *(const float*)((const char*)prow + extoff[5]);     \
        const float p3 = *(const float*)((const char*)prow + extoff[3]);     \
        const float p1 = *(const float*)((const char*)prow + extoff[1]);     \
        a[9] = fmaf(skipok[9], a[7], a[9] + a[8]) * p9;                      \
        a[8] = (a[8] + a[7]) * pB;                                           \
        a[7] = fmaf(skipok[7], a[5], a[7] + a[6]) * p7;                      \
        a[6] = (a[6] + a[5]) * pB;                                           \
        a[5] = fmaf(skipok[5], a[3], a[5] + a[4]) * p5;                      \
        a[4] = (a[4] + a[3]) * pB;                                           \
        a[3] = fmaf(skipok[3], a[1], a[3] + a[2]) * p3;                      \
        a[2] = (a[2] + a[1]) * pB;                                           \
        a[1] = fmaf(skipok[1], up, a[1] + a[0]) * p1;                        \
        a[0] = (a[0] + up) * pB;                                             \
        if (DORENORM) {                                                      \
            float m01 = fmaxf(a[0], a[1]), m23 = fmaxf(a[2], a[3]);          \
            float m45 = fmaxf(a[4], a[5]), m67 = fmaxf(a[6], a[7]);          \
            float m89 = fmaxf(a[8], a[9]);                                   \
            float m = fmaxf(fmaxf(fmaxf(m01, m23), fmaxf(m45, m67)), m89);   \
            int e_ = (m > 0.f) ? ((__float_as_int(m) >> 23) - 127) : 0;      \
            const float s_ = __int_as_float((127 - e_) << 23);               \
            a[0] *= s_; a[1] *= s_; a[2] *= s_; a[3] *= s_; a[4] *= s_;      \
            a[5] *= s_; a[6] *= s_; a[7] *= s_; a[8] *= s_; a[9] *= s_;      \
            E += e_;                                                         \
        }                                                                    \
    } while (0)

    for (int c = 0; c < nchunks; c++) {
        float* const buf = (c & 1) ? myb1 : myb0;

        // exp to linear probabilities, store to smem
        #pragma unroll
        for (int k = 0; k < 5; k++) {
            float4 v = rbuf[k];
            v.x = ex2f(v.x * LOG2E); v.y = ex2f(v.y * LOG2E);
            v.z = ex2f(v.z * LOG2E); v.w = ex2f(v.w * LOG2E);
            *(float4*)(buf + rr[k] * ROWSTRIDE + pq[k] * 4) = v;
        }
        if (lane < CHUNK) {
            *(float4*)(buf + lane * ROWSTRIDE + 80) = make_float4(0.f, 0.f, 0.f, 0.f);
        }

        if (c + 1 < nchunks) {
            const int t0 = 1 + (c + 1) * CHUNK;
            #pragma unroll
            for (int k = 0; k < 5; k++) {
                int t = t0 + rr[k]; if (t > TT - 1) t = TT - 1;
                const float4* src = (const float4*)(lp + ((size_t)t * NN + n) * CC);
                rbuf[k] = src[pq[k]];
            }
        }
        __syncwarp();

        if (c < nfull) {
            // branch-free 8 steps; renorm at r=3,7; frame refresh at cadence
            REFRESH();
            STEP(buf + 0 * ROWSTRIDE, false);
            STEP(buf + 1 * ROWSTRIDE, false);
            STEP(buf + 2 * ROWSTRIDE, false);
            STEP(buf + 3 * ROWSTRIDE, true);
            REFRESH();
            STEP(buf + 4 * ROWSTRIDE, false);
            STEP(buf + 5 * ROWSTRIDE, false);
            STEP(buf + 6 * ROWSTRIDE, false);
            STEP(buf + 7 * ROWSTRIDE, true);
        } else {
            const int ntail = totalSteps - c * CHUNK;
            for (int r = 0; r < ntail; r++) {
                REFRESH();
                STEP(buf + r * ROWSTRIDE, true);
            }
        }
    }

    #undef STEP
    #undef REFRESH

    // Readout: alpha at s = 2*tl and 2*tl-1 (may straddle two threads).
    #pragma unroll
    for (int j = 0; j < PPT; j++) salpha[warp][lane * PPT + j] = a[j];
    sE[warp][lane] = E;
    __syncwarp();
    if (lane == 0) {
        const int s1 = 2 * tl, s2 = 2 * tl - 1;
        const float v1 = salpha[warp][s1];
        const float v2 = salpha[warp][s2];
        const float l1 = lg2f(v1) + (float)sE[warp][s1 / PPT];
        const float l2 = lg2f(v2) + (float)sE[warp][s2 / PPT];
        float loss = -LN2 * lse2(l1, l2);
        if (!isfinite(loss) || loss >= 1e10f) loss = 0.f;
        out[n] = loss;
    }
}

extern "C" void kernel_launch(void* const* d_in, const int* in_sizes, int n_in,
                              void* d_out, int out_size) {
    const float* lp      = nullptr;
    const int*   targets = nullptr;
    const int*   lenA    = nullptr;
    const int*   lenB    = nullptr;
    for (int i = 0; i < n_in; i++) {
        const int sz = in_sizes[i];
        if (sz == TT * NN * CC)      lp      = (const float*)d_in[i];
        else if (sz == NN * SS)      targets = (const int*)d_in[i];
        else if (sz == NN) { if (!lenA) lenA = (const int*)d_in[i];
                             else       lenB = (const int*)d_in[i]; }
    }
    if (!lp)      lp      = (const float*)d_in[0];
    if (!targets) targets = (const int*)d_in[1];
    if (!lenA)    lenA    = (const int*)d_in[2];
    if (!lenB)    lenB    = (const int*)d_in[3];

    float* out = (float*)d_out;
    (void)out_size;
    ctc_kernel<<<NN / WPB, 32 * WPB>>>(lp, targets, lenA, lenB, out);
}

// round 7
// speedup vs baseline: 2.5572x; 1.1116x over previous
#include <cuda_runtime.h>
#include <math.h>

// CTC forward loss — linear-domain DP, per-thread integer-exponent frames
// (physical alpha = a' * 2^E). Renorm + frame refresh every 4 steps.
// Software-pipelined: emission probs for step r+1 load while step r computes;
// next step's shfl issues right after a[9] is produced.
// One warp per batch element; 10 lattice positions/thread (32*10=320>=257).

#define TT 512
#define NN 512
#define CC 80
#define SS 128
#define LL 257
#define PPT 10
#define ROWSTRIDE 84
#define CHUNK 16
#define WPB 4

#define LOG2E 1.4426950408889634f
#define LN2   0.6931471805599453f

__device__ __forceinline__ float ex2f(float x) {
    float r; asm("ex2.approx.ftz.f32 %0, %1;" : "=f"(r) : "f"(x)); return r;
}
__device__ __forceinline__ float lg2f(float x) {
    float r; asm("lg2.approx.ftz.f32 %0, %1;" : "=f"(r) : "f"(x)); return r;
}
__device__ __forceinline__ float lse2(float x, float y) {
    float m = fmaxf(x, y);
    float d = fminf(x, y) - m;
    return m + lg2f(1.0f + ex2f(d));
}

__global__ __launch_bounds__(128, 1)
void ctc_kernel(const float* __restrict__ lp,
                const int*   __restrict__ targets,
                const int*   __restrict__ lenA,
                const int*   __restrict__ lenB,
                float*       __restrict__ out)
{
    __shared__ __align__(16) float pbuf[WPB][CHUNK][ROWSTRIDE];
    __shared__ int   stgt[WPB][SS];
    __shared__ float salpha[WPB][32 * PPT];
    __shared__ int   sE[WPB][32];

    const int warp = threadIdx.x >> 5;
    const int lane = threadIdx.x & 31;
    const int n    = blockIdx.x * WPB + warp;

    // Length roles: ranges disjoint (T_in in [256,512], tl in [64,128]).
    const int la = lenA[n];
    const int lb = lenB[n];
    int T_in = la > lb ? la : lb;
    int tl   = la > lb ? lb : la;
    T_in = max(1, min(T_in, TT));
    tl   = max(1, min(tl, SS));

    for (int i = lane; i < SS; i += 32) {
        int y = targets[n * SS + i];
        stgt[warp][i] = max(0, min(y, CC - 1));
    }
    __syncwarp();

    // Lattice setup: s = lane*PPT + j; j parity == lattice parity.
    int   extoff[PPT];
    float skipok[PPT];
    float a[PPT];
    #pragma unroll
    for (int j = 0; j < PPT; j++) {
        const int s = lane * PPT + j;
        int e = 80; float sk = 0.f;
        if (s < LL) {
            if ((s & 1) == 0) e = 0;
            else {
                e = stgt[warp][(s - 1) >> 1];
                if (s >= 3) sk = (e != stgt[warp][(s - 3) >> 1]) ? 1.f : 0.f;
            }
        }
        extoff[j] = e * 4;
        skipok[j] = sk;
        a[j]      = 0.f;
    }

    int   E   = 0;
    float fup = 0.f;                 // 2^(Ep-E); 0 for lane 0
    bool  act = (lane == 0);         // sticky: thread has received mass
    float upn = 0.f;                 // shfl'd neighbor a[9] for the NEXT step

    if (lane == 0) {
        const float* row0 = lp + (size_t)n * CC;
        a[0] = ex2f(row0[0] * LOG2E);
        a[1] = ex2f(row0[stgt[warp][0]] * LOG2E);
    }

    // Chunk-load mapping: 16 rows x 20 float4 = 320 loads = 10 per lane.
    int rr[10], pq[10];
    #pragma unroll
    for (int k = 0; k < 10; k++) {
        const int q = lane + 32 * k;
        rr[k] = q / 20;
        pq[k] = q % 20;
    }

    float4 rbuf[10];
    #pragma unroll
    for (int k = 0; k < 10; k++) {     // prefetch chunk 0 (t = 1..16)
        int t = 1 + rr[k]; if (t > TT - 1) t = TT - 1;
        const float4* src = (const float4*)(lp + ((size_t)t * NN + n) * CC);
        rbuf[k] = src[pq[k]];
    }

    float* const buf = &pbuf[warp][0][0];

    const int totalSteps = T_in - 1;
    const int nchunks = (totalSteps + CHUNK - 1) / CHUNK;
    const int nfull   = totalSteps / CHUNK;

    #define LOADP(PV, prow) do {                                              \
        PV[0] = (prow)[0];                                                    \
        PV[1] = *(const float*)((const char*)(prow) + extoff[1]);             \
        PV[2] = *(const float*)((const char*)(prow) + extoff[3]);             \
        PV[3] = *(const float*)((const char*)(prow) + extoff[5]);             \
        PV[4] = *(const float*)((const char*)(prow) + extoff[7]);             \
        PV[5] = *(const float*)((const char*)(prow) + extoff[9]);             \
    } while (0)

    #define REFRESH() do {                                                    \
        int Ep_ = __shfl_up_sync(0xffffffffu, E, 1);                          \
        act = act || (a[0] != 0.f);                                           \
        if (!act) E = Ep_;                                                    \
        int dE_ = min(max(Ep_ - E, -126), 120);                               \
        fup = (lane == 0) ? 0.f : __int_as_float((dE_ + 127) << 23);          \
    } while (0)

    // Normal step: a[9] first, next-step shfl immediately, prefetch next p's.
    #define STEPN(PV, PN, nextrow) do {                                       \
        float up_ = upn * fup;                                                \
        float t9_ = fmaf(skipok[9], a[7], a[9] + a[8]) * PV[5];               \
        a[9] = t9_;                                                           \
        upn = __shfl_up_sync(0xffffffffu, t9_, 1);                            \
        LOADP(PN, nextrow);                                                   \
        a[8] = (a[8] + a[7]) * PV[0];                                         \
        a[7] = fmaf(skipok[7], a[5], a[7] + a[6]) * PV[4];                    \
        a[6] = (a[6] + a[5]) * PV[0];                                         \
        a[5] = fmaf(skipok[5], a[3], a[5] + a[4]) * PV[3];                    \
        a[4] = (a[4] + a[3]) * PV[0];                                         \
        a[3] = fmaf(skipok[3], a[1], a[3] + a[2]) * PV[2];                    \
        a[2] = (a[2] + a[1]) * PV[0];                                         \
        a[1] = fmaf(skipok[1], up_, a[1] + a[0]) * PV[1];                     \
        a[0] = (a[0] + up_) * PV[0];                                          \
    } while (0)

    // Renorm step body (shared): update, renorm, shfl post-scale a[9].
    #define STEPR_BODY(PV) do {                                               \
        float up_ = upn * fup;                                                \
        a[9] = fmaf(skipok[9], a[7], a[9] + a[8]) * PV[5];                    \
        a[8] = (a[8] + a[7]) * PV[0];                                         \
        a[7] = fmaf(skipok[7], a[5], a[7] + a[6]) * PV[4];                    \
        a[6] = (a[6] + a[5]) * PV[0];                                         \
        a[5] = fmaf(skipok[5], a[3], a[5] + a[4]) * PV[3];                    \
        a[4] = (a[4] + a[3]) * PV[0];                                         \
        a[3] = fmaf(skipok[3], a[1], a[3] + a[2]) * PV[2];                    \
        a[2] = (a[2] + a[1]) * PV[0];                                         \
        a[1] = fmaf(skipok[1], up_, a[1] + a[0]) * PV[1];                     \
        a[0] = (a[0] + up_) * PV[0];                                          \
        float m01 = fmaxf(a[0], a[1]), m23 = fmaxf(a[2], a[3]);               \
        float m45 = fmaxf(a[4], a[5]), m67 = fmaxf(a[6], a[7]);               \
        float m89 = fmaxf(a[8], a[9]);                                        \
        float m_ = fmaxf(fmaxf(m01, m23), fmaxf(fmaxf(m45, m67), m89));       \
        int e_ = (m_ > 0.f) ? ((__float_as_int(m_) >> 23) - 127) : 0;         \
        float s_ = __int_as_float((127 - e_) << 23);                          \
        a[9] *= s_;                                                           \
        upn = __shfl_up_sync(0xffffffffu, a[9], 1);                           \
        a[0] *= s_; a[1] *= s_; a[2] *= s_; a[3] *= s_; a[4] *= s_;           \
        a[5] *= s_; a[6] *= s_; a[7] *= s_; a[8] *= s_;                       \
        E += e_;                                                              \
    } while (0)

    #define STEPR(PV, PN, nextrow) do { LOADP(PN, nextrow); STEPR_BODY(PV); } while (0)
    #define STEPR_LAST(PV) STEPR_BODY(PV)

    for (int c = 0; c < nchunks; c++) {
        // exp to linear probabilities, store chunk rows to smem
        #pragma unroll
        for (int k = 0; k < 10; k++) {
            float4 v = rbuf[k];
            v.x = ex2f(v.x * LOG2E); v.y = ex2f(v.y * LOG2E);
            v.z = ex2f(v.z * LOG2E); v.w = ex2f(v.w * LOG2E);
            *(float4*)(buf + rr[k] * ROWSTRIDE + pq[k] * 4) = v;
        }
        if (lane < CHUNK) {
            *(float4*)(buf + lane * ROWSTRIDE + 80) = make_float4(0.f, 0.f, 0.f, 0.f);
        }

        if (c + 1 < nchunks) {            // prefetch next chunk into registers
            const int t0 = 1 + (c + 1) * CHUNK;
            #pragma unroll
            for (int k = 0; k < 10; k++) {
                int t = t0 + rr[k]; if (t > TT - 1) t = TT - 1;
                const float4* src = (const float4*)(lp + ((size_t)t * NN + n) * CC);
                rbuf[k] = src[pq[k]];
            }
        }
        __syncwarp();

        if (c < nfull) {
            float P0[6], P1[6];
            LOADP(P0, buf);
            REFRESH();
            STEPN(P0, P1, buf + 1 * ROWSTRIDE);
            STEPN(P1, P0, buf + 2 * ROWSTRIDE);
            STEPN(P0, P1, buf + 3 * ROWSTRIDE);
            STEPR(P1, P0, buf + 4 * ROWSTRIDE);
            REFRESH();
            STEPN(P0, P1, buf + 5 * ROWSTRIDE);
            STEPN(P1, P0, buf + 6 * ROWSTRIDE);
            STEPN(P0, P1, buf + 7 * ROWSTRIDE);
            STEPR(P1, P0, buf + 8 * ROWSTRIDE);
            REFRESH();
            STEPN(P0, P1, buf + 9 * ROWSTRIDE);
            STEPN(P1, P0, buf + 10 * ROWSTRIDE);
            STEPN(P0, P1, buf + 11 * ROWSTRIDE);
            STEPR(P1, P0, buf + 12 * ROWSTRIDE);
            REFRESH();
            STEPN(P0, P1, buf + 13 * ROWSTRIDE);
            STEPN(P1, P0, buf + 14 * ROWSTRIDE);
            STEPN(P0, P1, buf + 15 * ROWSTRIDE);
            STEPR_LAST(P1);
        } else {
            const int ntail = totalSteps - c * CHUNK;
            for (int r = 0; r < ntail; r++) {
                float P0[6];
                LOADP(P0, buf + r * ROWSTRIDE);
                REFRESH();
                STEPR_LAST(P0);
            }
        }
    }

    #undef STEPN
    #undef STEPR
    #undef STEPR_BODY
    #undef STEPR_LAST
    #undef REFRESH
    #undef LOADP

    // Readout: alpha at s = 2*tl and 2*tl-1 (may straddle two threads).
    #pragma unroll
    for (int j = 0; j < PPT; j++) salpha[warp][lane * PPT + j] = a[j];
    sE[warp][lane] = E;
    __syncwarp();
    if (lane == 0) {
        const int s1 = 2 * tl, s2 = 2 * tl - 1;
        const float v1 = salpha[warp][s1];
        const float v2 = salpha[warp][s2];
        const float l1 = lg2f(v1) + (float)sE[warp][s1 / PPT];
        const float l2 = lg2f(v2) + (float)sE[warp][s2 / PPT];
        float loss = -LN2 * lse2(l1, l2);
        if (!isfinite(loss) || loss >= 1e10f) loss = 0.f;
        out[n] = loss;
    }
}

extern "C" void kernel_launch(void* const* d_in, const int* in_sizes, int n_in,
                              void* d_out, int out_size) {
    const float* lp      = nullptr;
    const int*   targets = nullptr;
    const int*   lenA    = nullptr;
    const int*   lenB    = nullptr;
    for (int i = 0; i < n_in; i++) {
        const int sz = in_sizes[i];
        if (sz == TT * NN * CC)      lp      = (const float*)d_in[i];
        else if (sz == NN * SS)      targets = (const int*)d_in[i];
        else if (sz == NN) { if (!lenA) lenA = (const int*)d_in[i];
                             else       lenB = (const int*)d_in[i]; }
    }
    if (!lp)      lp      = (const float*)d_in[0];
    if (!targets) targets = (const int*)d_in[1];
    if (!lenA)    lenA    = (const int*)d_in[2];
    if (!lenB)    lenB    = (const int*)d_in[3];

    float* out = (float*)d_out;
    (void)out_size;
    ctc_kernel<<<NN / WPB, 32 * WPB>>>(lp, targets, lenA, lenB, out);
}

// round 8
// speedup vs baseline: 2.9638x; 1.1590x over previous
#include <cuda_runtime.h>
#include <math.h>

// CTC forward loss — linear-domain DP, per-thread integer-exponent frames
// (physical alpha = a' * 2^E). Renorm + frame refresh every 4 steps.
// Fully software-pipelined 3-stage chunk pipeline:
//   chunk c   : DP steps (smem buf c&1)
//   chunk c+1 : ex2 convert + STS into buf (c+1)&1, spread over c's steps
//   chunk c+2 : LDG raw rows into rbuf[k] right after EXPSTEP(k) frees it
// One warp per batch element; 10 lattice positions/thread (32*10=320>=257).
// Fake cells (s>=257) alias class 0: they never feed real cells, renorm
// scale choice is E-compensated, readout reads real cells only.

#define TT 512
#define NN 512
#define CC 80
#define SS 128
#define LL 257
#define PPT 10
#define RS 80            // row stride in floats (no pad slot)
#define CHUNK 16
#define WPB 4

#define LOG2E 1.4426950408889634f
#define LN2   0.6931471805599453f

__device__ __forceinline__ float ex2f(float x) {
    float r; asm("ex2.approx.ftz.f32 %0, %1;" : "=f"(r) : "f"(x)); return r;
}
__device__ __forceinline__ float lg2f(float x) {
    float r; asm("lg2.approx.ftz.f32 %0, %1;" : "=f"(r) : "f"(x)); return r;
}
__device__ __forceinline__ float lse2(float x, float y) {
    float m = fmaxf(x, y);
    float d = fminf(x, y) - m;
    return m + lg2f(1.0f + ex2f(d));
}

__global__ __launch_bounds__(128, 1)
void ctc_kernel(const float* __restrict__ lp,
                const int*   __restrict__ targets,
                const int*   __restrict__ lenA,
                const int*   __restrict__ lenB,
                float*       __restrict__ out)
{
    __shared__ __align__(16) float pbuf[WPB][2][CHUNK][RS];
    __shared__ int   stgt[WPB][SS];
    __shared__ float salpha[WPB][32 * PPT];
    __shared__ int   sE[WPB][32];

    const int warp = threadIdx.x >> 5;
    const int lane = threadIdx.x & 31;
    const int n    = blockIdx.x * WPB + warp;

    // Length roles: ranges disjoint (T_in in [256,512], tl in [64,128]).
    const int la = lenA[n];
    const int lb = lenB[n];
    int T_in = la > lb ? la : lb;
    int tl   = la > lb ? lb : la;
    T_in = max(1, min(T_in, TT));
    tl   = max(1, min(tl, SS));

    for (int i = lane; i < SS; i += 32) {
        int y = targets[n * SS + i];
        stgt[warp][i] = max(0, min(y, CC - 1));
    }
    __syncwarp();

    // Lattice setup: s = lane*PPT + j; j parity == lattice parity.
    int   extoff[PPT];
    float skipok[PPT];
    float a[PPT];
    #pragma unroll
    for (int j = 0; j < PPT; j++) {
        const int s = lane * PPT + j;
        int e = 0; float sk = 0.f;          // fake cells alias class 0
        if (s < LL && (s & 1)) {
            e = stgt[warp][(s - 1) >> 1];
            if (s >= 3) sk = (e != stgt[warp][(s - 3) >> 1]) ? 1.f : 0.f;
        }
        extoff[j] = e * 4;
        skipok[j] = sk;
        a[j]      = 0.f;
    }

    int   E   = 0;
    float fup = 0.f;                 // 2^(Ep-E); 0 for lane 0
    bool  act = (lane == 0);         // sticky: thread has received mass
    float upn = 0.f;                 // shfl'd neighbor a[9] for the NEXT step

    if (lane == 0) {
        const float* row0 = lp + (size_t)n * CC;
        a[0] = ex2f(row0[0] * LOG2E);
        a[1] = ex2f(row0[stgt[warp][0]] * LOG2E);
    }

    // Chunk-load mapping: 16 rows x 20 float4 = 320 loads = 10 per lane.
    int rr[10], pq[10];
    #pragma unroll
    for (int k = 0; k < 10; k++) {
        const int q = lane + 32 * k;
        rr[k] = q / 20;
        pq[k] = q % 20;
    }

    float* const buf0 = &pbuf[warp][0][0][0];
    float* const buf1 = &pbuf[warp][1][0][0];

    const int totalSteps = T_in - 1;
    const int nchunks = (totalSteps + CHUNK - 1) / CHUNK;
    const int nfull   = totalSteps / CHUNK;

    // Prologue: raw chunk 0 -> exp into buf0; raw chunk 1 -> rbuf.
    float4 rbuf[10];
    #pragma unroll
    for (int k = 0; k < 10; k++) {
        int t = 1 + rr[k]; if (t > TT - 1) t = TT - 1;
        rbuf[k] = *(const float4*)(lp + ((size_t)t * NN + n) * CC + pq[k] * 4);
    }
    #pragma unroll
    for (int k = 0; k < 10; k++) {
        float4 v = rbuf[k];
        v.x = ex2f(v.x * LOG2E); v.y = ex2f(v.y * LOG2E);
        v.z = ex2f(v.z * LOG2E); v.w = ex2f(v.w * LOG2E);
        *(float4*)(buf0 + rr[k] * RS + pq[k] * 4) = v;
    }
    #pragma unroll
    for (int k = 0; k < 10; k++) {
        int t = 1 + CHUNK + rr[k]; if (t > TT - 1) t = TT - 1;
        rbuf[k] = *(const float4*)(lp + ((size_t)t * NN + n) * CC + pq[k] * 4);
    }
    __syncwarp();

    #define LOADP(PV, prow) do {                                              \
        PV[0] = (prow)[0];                                                    \
        PV[1] = *(const float*)((const char*)(prow) + extoff[1]);             \
        PV[2] = *(const float*)((const char*)(prow) + extoff[3]);             \
        PV[3] = *(const float*)((const char*)(prow) + extoff[5]);             \
        PV[4] = *(const float*)((const char*)(prow) + extoff[7]);             \
        PV[5] = *(const float*)((const char*)(prow) + extoff[9]);             \
    } while (0)

    #define REFRESH() do {                                                    \
        int Ep_ = __shfl_up_sync(0xffffffffu, E, 1);                          \
        act = act || (a[0] != 0.f);                                           \
        if (!act) E = Ep_;                                                    \
        int dE_ = min(max(Ep_ - E, -126), 120);                               \
        fup = (lane == 0) ? 0.f : __int_as_float((dE_ + 127) << 23);          \
    } while (0)

    // Convert rbuf[k] (chunk c+1) -> nbuf, then refill rbuf[k] with chunk c+2.
    #define EXPSTEP(k) do {                                                   \
        float4 v_ = rbuf[k];                                                  \
        v_.x = ex2f(v_.x * LOG2E); v_.y = ex2f(v_.y * LOG2E);                 \
        v_.z = ex2f(v_.z * LOG2E); v_.w = ex2f(v_.w * LOG2E);                 \
        *(float4*)(nbuf + rr[k] * RS + pq[k] * 4) = v_;                       \
        int t_ = tldg + rr[k]; if (t_ > TT - 1) t_ = TT - 1;                  \
        rbuf[k] = *(const float4*)(lp + ((size_t)t_ * NN + n) * CC + pq[k] * 4); \
    } while (0)

    #define STEPN(PV, PN, nextrow) do {                                       \
        float up_ = upn * fup;                                                \
        float t9_ = fmaf(skipok[9], a[7], a[9] + a[8]) * PV[5];               \
        a[9] = t9_;                                                           \
        upn = __shfl_up_sync(0xffffffffu, t9_, 1);                            \
        LOADP(PN, nextrow);                                                   \
        a[8] = (a[8] + a[7]) * PV[0];                                         \
        a[7] = fmaf(skipok[7], a[5], a[7] + a[6]) * PV[4];                    \
        a[6] = (a[6] + a[5]) * PV[0];                                         \
        a[5] = fmaf(skipok[5], a[3], a[5] + a[4]) * PV[3];                    \
        a[4] = (a[4] + a[3]) * PV[0];                                         \
        a[3] = fmaf(skipok[3], a[1], a[3] + a[2]) * PV[2];                    \
        a[2] = (a[2] + a[1]) * PV[0];                                         \
        a[1] = fmaf(skipok[1], up_, a[1] + a[0]) * PV[1];                     \
        a[0] = (a[0] + up_) * PV[0];                                          \
    } while (0)

    #define STEPR_BODY(PV) do {                                               \
        float up_ = upn * fup;                                                \
        a[9] = fmaf(skipok[9], a[7], a[9] + a[8]) * PV[5];                    \
        a[8] = (a[8] + a[7]) * PV[0];                                         \
        a[7] = fmaf(skipok[7], a[5], a[7] + a[6]) * PV[4];                    \
        a[6] = (a[6] + a[5]) * PV[0];                                         \
        a[5] = fmaf(skipok[5], a[3], a[5] + a[4]) * PV[3];                    \
        a[4] = (a[4] + a[3]) * PV[0];                                         \
        a[3] = fmaf(skipok[3], a[1], a[3] + a[2]) * PV[2];                    \
        a[2] = (a[2] + a[1]) * PV[0];                                         \
        a[1] = fmaf(skipok[1], up_, a[1] + a[0]) * PV[1];                     \
        a[0] = (a[0] + up_) * PV[0];                                          \
        float m01 = fmaxf(a[0], a[1]), m23 = fmaxf(a[2], a[3]);               \
        float m45 = fmaxf(a[4], a[5]), m67 = fmaxf(a[6], a[7]);               \
        float m89 = fmaxf(a[8], a[9]);                                        \
        float m_ = fmaxf(fmaxf(m01, m23), fmaxf(fmaxf(m45, m67), m89));       \
        int e_ = (m_ > 0.f) ? ((__float_as_int(m_) >> 23) - 127) : 0;         \
        float s_ = __int_as_float((127 - e_) << 23);                          \
        a[9] *= s_;                                                           \
        upn = __shfl_up_sync(0xffffffffu, a[9], 1);                           \
        a[0] *= s_; a[1] *= s_; a[2] *= s_; a[3] *= s_; a[4] *= s_;           \
        a[5] *= s_; a[6] *= s_; a[7] *= s_; a[8] *= s_;                       \
        E += e_;                                                              \
    } while (0)

    #define STEPR(PV, PN, nextrow) do { LOADP(PN, nextrow); STEPR_BODY(PV); } while (0)

    for (int c = 0; c < nfull; c++) {
        float* const buf  = (c & 1) ? buf1 : buf0;
        float* const nbuf = (c & 1) ? buf0 : buf1;
        const int tldg = 1 + (c + 2) * CHUNK;

        float P0[6], P1[6];
        LOADP(P0, buf);
        REFRESH();
        STEPN(P0, P1, buf + 1 * RS);  EXPSTEP(0);
        STEPN(P1, P0, buf + 2 * RS);  EXPSTEP(1);
        STEPN(P0, P1, buf + 3 * RS);  EXPSTEP(2);
        STEPR(P1, P0, buf + 4 * RS);  EXPSTEP(3);
        REFRESH();
        STEPN(P0, P1, buf + 5 * RS);  EXPSTEP(4);
        STEPN(P1, P0, buf + 6 * RS);  EXPSTEP(5);
        STEPN(P0, P1, buf + 7 * RS);  EXPSTEP(6);
        STEPR(P1, P0, buf + 8 * RS);  EXPSTEP(7);
        REFRESH();
        STEPN(P0, P1, buf + 9 * RS);  EXPSTEP(8);
        STEPN(P1, P0, buf + 10 * RS); EXPSTEP(9);
        STEPN(P0, P1, buf + 11 * RS);
        STEPR(P1, P0, buf + 12 * RS);
        REFRESH();
        STEPN(P0, P1, buf + 13 * RS);
        STEPN(P1, P0, buf + 14 * RS);
        STEPN(P0, P1, buf + 15 * RS);
        STEPR_BODY(P1);
        __syncwarp();
    }

    // Tail: remaining steps from buf[nfull&1] (filled by EXPSTEPs).
    {
        const int ntail = totalSteps - nfull * CHUNK;
        float* const buf = (nfull & 1) ? buf1 : buf0;
        for (int r = 0; r < ntail; r++) {
            float P0[6];
            LOADP(P0, buf + r * RS);
            REFRESH();
            STEPR_BODY(P0);
        }
    }

    #undef STEPN
    #undef STEPR
    #undef STEPR_BODY
    #undef REFRESH
    #undef LOADP
    #undef EXPSTEP

    // Readout: alpha at s = 2*tl and 2*tl-1 (may straddle two threads).
    #pragma unroll
    for (int j = 0; j < PPT; j++) salpha[warp][lane * PPT + j] = a[j];
    sE[warp][lane] = E;
    __syncwarp();
    if (lane == 0) {
        const int s1 = 2 * tl, s2 = 2 * tl - 1;
        const float v1 = salpha[warp][s1];
        const float v2 = salpha[warp][s2];
        const float l1 = lg2f(v1) + (float)sE[warp][s1 / PPT];
        const float l2 = lg2f(v2) + (float)sE[warp][s2 / PPT];
        float loss = -LN2 * lse2(l1, l2);
        if (!isfinite(loss) || loss >= 1e10f) loss = 0.f;
        out[n] = loss;
    }
}

extern "C" void kernel_launch(void* const* d_in, const int* in_sizes, int n_in,
                              void* d_out, int out_size) {
    const float* lp      = nullptr;
    const int*   targets = nullptr;
    const int*   lenA    = nullptr;
    const int*   lenB    = nullptr;
    for (int i = 0; i < n_in; i++) {
        const int sz = in_sizes[i];
        if (sz == TT * NN * CC)      lp      = (const float*)d_in[i];
        else if (sz == NN * SS)      targets = (const int*)d_in[i];
        else if (sz == NN) { if (!lenA) lenA = (const int*)d_in[i];
                             else       lenB = (const int*)d_in[i]; }
    }
    if (!lp)      lp      = (const float*)d_in[0];
    if (!targets) targets = (const int*)d_in[1];
    if (!lenA)    lenA    = (const int*)d_in[2];
    if (!lenB)    lenB    = (const int*)d_in[3];

    float* out = (float*)d_out;
    (void)out_size;
    ctc_kernel<<<NN / WPB, 32 * WPB>>>(lp, targets, lenA, lenB, out);
}